// round 7
// baseline (speedup 1.0000x reference)
#include <cuda_runtime.h>

// Problem constants
#define BATCH 8
#define CIN   256
#define COUT  256
#define H     64
#define W     64
#define S     4096        // H*W
#define K2    9
#define R     2304        // CIN*K2

// Scratch: x transposed to [b][s][c], raw fp32 (33.5 MB)
__device__ float g_xt[(size_t)BATCH * S * CIN];
// Scratch: weights, tf32-rounded, reordered to [o][k2*256 + c]
__device__ float g_wt[(size_t)COUT * R];

__device__ __forceinline__ unsigned f2tf(float f) {
    unsigned r;
    asm("cvt.rna.tf32.f32 %0, %1;" : "=r"(r) : "f"(f));
    return r;
}

// ---------------------------------------------------------------------------
// Kernel 0: weight prepack: g_wt[o][k2*256+c] = tf32(w[o][c][k2])
// ---------------------------------------------------------------------------
__global__ void __launch_bounds__(512) cvtw_k(const float* __restrict__ w) {
    const int j   = blockIdx.x * 512 + threadIdx.x;   // COUT*R = 1152*512
    const int o   = j / R;
    const int rem = j - o * R;
    const int k2  = rem >> 8;
    const int c   = rem & 255;
    g_wt[j] = __uint_as_float(f2tf(w[o * R + c * 9 + k2]));
}

// ---------------------------------------------------------------------------
// Kernel 1: transpose x[b][c][s] -> g_xt[b][s][c]  (raw fp32)
// ---------------------------------------------------------------------------
__global__ void __launch_bounds__(256) trans_k(const float* __restrict__ x) {
    __shared__ float t[32][33];
    const int b  = blockIdx.z;
    const int s0 = blockIdx.x * 32;
    const int c0 = blockIdx.y * 32;
    const int tx = threadIdx.x, ty = threadIdx.y;
    const float* xb = x + ((size_t)b << 20);
#pragma unroll
    for (int i = ty; i < 32; i += 8)
        t[i][tx] = xb[(size_t)(c0 + i) * S + s0 + tx];
    __syncthreads();
    float* xtb = g_xt + ((size_t)b << 20);
#pragma unroll
    for (int i = ty; i < 32; i += 8)
        xtb[(size_t)(s0 + i) * CIN + c0 + tx] = t[tx][i];
}

// ---------------------------------------------------------------------------
// Kernel 2: fused deform-gather + GEMM
//   out[b] (256 x 4096) = g_wt (256 x 2304) * B[b] (2304 x 4096)
//   B built on the fly per 32x128 k-tile from g_xt + bilinear table.
// Block: M=256 (all), N=128, 512 threads, 16 warps (4M x 4N), warp 64x32.
// ---------------------------------------------------------------------------
#define KTILE 32
#define NKT   72
#define A_LD  36                   // conflict-free A frag loads
#define B_LD  132                  // conflict-free B frag loads
#define A_BUF (256 * A_LD)         // 9216 words
#define B_BUF (KTILE * B_LD)       // 4224 words
#define TBL_OFF (2 * A_BUF + 2 * B_BUF)        // 26880 words
#define SMEM_WORDS (TBL_OFF + 1152 * 8)        // + table (uint4+float4)*1152
#define SMEM_BYTES (SMEM_WORDS * 4)            // 144,384 B

#define CP_ASYNC16(dst, src) \
    asm volatile("cp.async.cg.shared.global [%0], [%1], 16;\n" :: "r"(dst), "l"(src))
#define CP_COMMIT() asm volatile("cp.async.commit_group;\n")
#define CP_WAIT0()  asm volatile("cp.async.wait_group 0;\n")

__device__ __forceinline__ void mma8(float* c, const unsigned* a, const unsigned* b) {
    asm volatile(
        "mma.sync.aligned.m16n8k8.row.col.f32.tf32.tf32.f32 "
        "{%0,%1,%2,%3}, {%4,%5,%6,%7}, {%8,%9}, {%0,%1,%2,%3};\n"
        : "+f"(c[0]), "+f"(c[1]), "+f"(c[2]), "+f"(c[3])
        : "r"(a[0]), "r"(a[1]), "r"(a[2]), "r"(a[3]), "r"(b[0]), "r"(b[1]));
}

__global__ void __launch_bounds__(512, 1) gemm_k(const float* __restrict__ off,
                                                 float* __restrict__ out) {
    extern __shared__ unsigned sm[];
    uint4*  tbl_i = (uint4*)(sm + TBL_OFF);
    float4* tbl_w = (float4*)(sm + TBL_OFF + 1152 * 4);

    const int b     = blockIdx.z;
    const int nBase = blockIdx.x * 128;
    const int tid   = threadIdx.x;
    const int warp  = tid >> 5;
    const int lane  = tid & 31;
    const int wm    = (warp >> 2) * 64;
    const int wn    = (warp & 3) * 32;
    const int g     = lane >> 2;
    const int tig   = lane & 3;

    // ---- bilinear table: 128 s x 9 k2 -> 4 idx + 4 weights ----
    for (int e = tid; e < 1152; e += 512) {
        const int s_l = e / 9;
        const int k2  = e - s_l * 9;
        const int s   = nBase + s_l;
        const int ho  = s >> 6, wo = s & 63;
        const float dy = off[((size_t)b * 18 + 2 * k2)     * S + s];
        const float dx = off[((size_t)b * 18 + 2 * k2 + 1) * S + s];
        const float py = (float)(ho - 1 + k2 / 3) + dy;
        const float px = (float)(wo - 1 + k2 % 3) + dx;
        const float yf = floorf(py), xf = floorf(px);
        const int y0 = (int)yf, x0 = (int)xf;
        const float ly = py - yf, lx = px - xf;
        const float hy = 1.0f - ly, hx = 1.0f - lx;
        const bool vy0 = (y0 >= 0)  && (y0 < H);
        const bool vy1 = (y0 >= -1) && (y0 < H - 1);
        const bool vx0 = (x0 >= 0)  && (x0 < W);
        const bool vx1 = (x0 >= -1) && (x0 < W - 1);
        const float w00 = hy * hx * (float)(vy0 && vx0);
        const float w01 = hy * lx * (float)(vy0 && vx1);
        const float w10 = ly * hx * (float)(vy1 && vx0);
        const float w11 = ly * lx * (float)(vy1 && vx1);
        const int cy0 = min(max(y0, 0), H - 1);
        const int cy1 = min(max(y0 + 1, 0), H - 1);
        const int cx0 = min(max(x0, 0), W - 1);
        const int cx1 = min(max(x0 + 1, 0), W - 1);
        tbl_i[e] = make_uint4((cy0 << 6) + cx0, (cy0 << 6) + cx1,
                              (cy1 << 6) + cx0, (cy1 << 6) + cx1);
        tbl_w[e] = make_float4(w00, w01, w10, w11);
    }
    __syncthreads();

    const unsigned smem_base = (unsigned)__cvta_generic_to_shared(sm);
    const int arow = tid >> 3;          // 0..63
    const int acol = (tid & 7) * 4;     // 0..28
    const int q    = tid & 7;           // c-quad within k-tile
    const int sl0  = tid >> 3;          // 0..63 (s within tile; +64 for grp 1)
    const float* Xb = g_xt + ((size_t)b << 20);

    float acc[4][4][4];
#pragma unroll
    for (int i = 0; i < 4; i++)
#pragma unroll
        for (int j = 0; j < 4; j++)
#pragma unroll
            for (int k = 0; k < 4; k++) acc[i][j][k] = 0.0f;

    // ---- prologue: A(0) via cp.async, B(0) built serially ----
#pragma unroll
    for (int p = 0; p < 4; p++)
        CP_ASYNC16(smem_base + (((p * 64 + arow) * A_LD + acol) << 2),
                   g_wt + (size_t)(p * 64 + arow) * R + acol);
    CP_COMMIT();
    {
        unsigned* Bd = sm + 2 * A_BUF;          // B buf 0
#pragma unroll
        for (int grp = 0; grp < 2; grp++) {
            const int s_l = sl0 + grp * 64;
            const int e = s_l * 9;              // k2 = 0
            uint4 ii = tbl_i[e];
            float4 wv = tbl_w[e];
            const float* base = Xb + q * 4;     // c0 = 0
            float4 a0 = *(const float4*)(base + ((size_t)ii.x << 8));
            float4 a1 = *(const float4*)(base + ((size_t)ii.y << 8));
            float4 a2 = *(const float4*)(base + ((size_t)ii.z << 8));
            float4 a3 = *(const float4*)(base + ((size_t)ii.w << 8));
            float4 v;
            v.x = wv.x * a0.x + wv.y * a1.x + wv.z * a2.x + wv.w * a3.x;
            v.y = wv.x * a0.y + wv.y * a1.y + wv.z * a2.y + wv.w * a3.y;
            v.z = wv.x * a0.z + wv.y * a1.z + wv.z * a2.z + wv.w * a3.z;
            v.w = wv.x * a0.w + wv.y * a1.w + wv.z * a2.w + wv.w * a3.w;
            Bd[(q * 4 + 0) * B_LD + s_l] = f2tf(v.x);
            Bd[(q * 4 + 1) * B_LD + s_l] = f2tf(v.y);
            Bd[(q * 4 + 2) * B_LD + s_l] = f2tf(v.z);
            Bd[(q * 4 + 3) * B_LD + s_l] = f2tf(v.w);
        }
    }
    CP_WAIT0();
    __syncthreads();

    // ---- main loop: build kt+1 interleaved with MMAs of kt ----
    auto mma_ks = [&](const unsigned* A, const unsigned* Bm, int ks) {
        const int kk = ks * 8 + tig;
        unsigned af[4][4], bf[4][2];
#pragma unroll
        for (int mt = 0; mt < 4; mt++) {
            const int mr = wm + mt * 16 + g;
            af[mt][0] = A[mr * A_LD + kk];
            af[mt][1] = A[(mr + 8) * A_LD + kk];
            af[mt][2] = A[mr * A_LD + kk + 4];
            af[mt][3] = A[(mr + 8) * A_LD + kk + 4];
        }
#pragma unroll
        for (int nt = 0; nt < 4; nt++) {
            const int nc = wn + nt * 8 + g;
            bf[nt][0] = Bm[kk * B_LD + nc];
            bf[nt][1] = Bm[(kk + 4) * B_LD + nc];
        }
#pragma unroll
        for (int mt = 0; mt < 4; mt++)
#pragma unroll
            for (int nt = 0; nt < 4; nt++)
                mma8(acc[mt][nt], af[mt], bf[nt]);
    };

    int cur = 0;
    for (int kt = 0; kt < NKT; kt++) {
        const bool more = (kt + 1 < NKT);
        uint4 ii0, ii1;
        const float* baseN = Xb;
        int eN0 = 0, eN1 = 0;
        float4 c00, c01, c10, c11;
        if (more) {
            const int ktn = kt + 1;
            const unsigned sa = smem_base + (cur ^ 1) * (A_BUF * 4);
            const int kb = ktn * KTILE;
#pragma unroll
            for (int p = 0; p < 4; p++)
                CP_ASYNC16(sa + (((p * 64 + arow) * A_LD + acol) << 2),
                           g_wt + (size_t)(p * 64 + arow) * R + kb + acol);
            CP_COMMIT();
            const int k2n = ktn >> 3;
            const int c0n = (ktn & 7) << 5;
            baseN = Xb + c0n + q * 4;
            eN0 = sl0 * 9 + k2n;
            eN1 = (sl0 + 64) * 9 + k2n;
            ii0 = tbl_i[eN0];
            ii1 = tbl_i[eN1];
            c00 = *(const float4*)(baseN + ((size_t)ii0.x << 8));
            c01 = *(const float4*)(baseN + ((size_t)ii0.y << 8));
            c10 = *(const float4*)(baseN + ((size_t)ii1.x << 8));
            c11 = *(const float4*)(baseN + ((size_t)ii1.y << 8));
        }

        const unsigned* A  = sm + cur * A_BUF;
        const unsigned* Bm = sm + 2 * A_BUF + cur * B_BUF;

        mma_ks(A, Bm, 0);
        mma_ks(A, Bm, 1);

        float4 v0, v1, w0, w1;
        if (more) {
            w0 = tbl_w[eN0];
            w1 = tbl_w[eN1];
            v0.x = w0.x * c00.x + w0.y * c01.x;  v0.y = w0.x * c00.y + w0.y * c01.y;
            v0.z = w0.x * c00.z + w0.y * c01.z;  v0.w = w0.x * c00.w + w0.y * c01.w;
            v1.x = w1.x * c10.x + w1.y * c11.x;  v1.y = w1.x * c10.y + w1.y * c11.y;
            v1.z = w1.x * c10.z + w1.y * c11.z;  v1.w = w1.x * c10.w + w1.y * c11.w;
            c00 = *(const float4*)(baseN + ((size_t)ii0.z << 8));
            c01 = *(const float4*)(baseN + ((size_t)ii0.w << 8));
            c10 = *(const float4*)(baseN + ((size_t)ii1.z << 8));
            c11 = *(const float4*)(baseN + ((size_t)ii1.w << 8));
        }

        mma_ks(A, Bm, 2);
        mma_ks(A, Bm, 3);

        if (more) {
            v0.x += w0.z * c00.x + w0.w * c01.x;  v0.y += w0.z * c00.y + w0.w * c01.y;
            v0.z += w0.z * c00.z + w0.w * c01.z;  v0.w += w0.z * c00.w + w0.w * c01.w;
            v1.x += w1.z * c10.x + w1.w * c11.x;  v1.y += w1.z * c10.y + w1.w * c11.y;
            v1.z += w1.z * c10.z + w1.w * c11.z;  v1.w += w1.z * c10.w + w1.w * c11.w;
            unsigned* Bd = sm + 2 * A_BUF + (cur ^ 1) * B_BUF;
            Bd[(q * 4 + 0) * B_LD + sl0] = f2tf(v0.x);
            Bd[(q * 4 + 1) * B_LD + sl0] = f2tf(v0.y);
            Bd[(q * 4 + 2) * B_LD + sl0] = f2tf(v0.z);
            Bd[(q * 4 + 3) * B_LD + sl0] = f2tf(v0.w);
            Bd[(q * 4 + 0) * B_LD + sl0 + 64] = f2tf(v1.x);
            Bd[(q * 4 + 1) * B_LD + sl0 + 64] = f2tf(v1.y);
            Bd[(q * 4 + 2) * B_LD + sl0 + 64] = f2tf(v1.z);
            Bd[(q * 4 + 3) * B_LD + sl0 + 64] = f2tf(v1.w);
        }
        CP_WAIT0();
        __syncthreads();
        cur ^= 1;
    }

    // ---- epilogue ----
    float* ob = out + (size_t)b * COUT * S + nBase;
#pragma unroll
    for (int mt = 0; mt < 4; mt++) {
#pragma unroll
        for (int nt = 0; nt < 4; nt++) {
            const int mr = wm + mt * 16 + g;
            const int nc = wn + nt * 8 + 2 * tig;
            *(float2*)(ob + (size_t)mr * S + nc) =
                make_float2(acc[mt][nt][0], acc[mt][nt][1]);
            *(float2*)(ob + (size_t)(mr + 8) * S + nc) =
                make_float2(acc[mt][nt][2], acc[mt][nt][3]);
        }
    }
}

// ---------------------------------------------------------------------------
extern "C" void kernel_launch(void* const* d_in, const int* in_sizes, int n_in,
                              void* d_out, int out_size) {
    const float* x   = (const float*)d_in[0];
    const float* off = (const float*)d_in[1];
    const float* wt  = (const float*)d_in[2];
    float* out       = (float*)d_out;

    cvtw_k<<<(COUT * R) / 512, 512>>>(wt);
    trans_k<<<dim3(S / 32, CIN / 32, BATCH), dim3(32, 8)>>>(x);

    cudaFuncSetAttribute(gemm_k, cudaFuncAttributeMaxDynamicSharedMemorySize,
                         SMEM_BYTES);
    gemm_k<<<dim3(S / 128, 1, BATCH), 512, SMEM_BYTES>>>(off, out);
}

// round 9
// speedup vs baseline: 1.4938x; 1.4938x over previous
#include <cuda_runtime.h>
#include <cstdint>

// Problem constants
#define BATCH 8
#define CIN   256
#define COUT  256
#define H     64
#define W     64
#define S     4096
#define K2    9
#define R     2304        // CIN*K2

// Scratch
__device__ float g_xt[(size_t)BATCH * S * CIN];     // x NHWC (raw fp32)
__device__ float g_colT[(size_t)BATCH * S * R];     // colT[b][s][k2*256+c], tf32-rounded
__device__ float g_wtp[(size_t)(R / 8) * COUT * 8]; // W permuted: [r/8][o][octet-interleaved]

__device__ __forceinline__ unsigned f2tf(float f) {
    unsigned r;
    asm("cvt.rna.tf32.f32 %0, %1;" : "=r"(r) : "f"(f));
    return r;
}

// ---------------------------------------------------------------------------
// Kernel 0: weight prepack into fragment-friendly permuted layout.
//   g_wtp[r>>3][o][slot] = tf32(w[o][c][k2]),  r = k2*256 + c,
//   slot = ((r&3)<<1) | ((r&7)>>2)   (octet order 0,4,1,5,2,6,3,7)
// ---------------------------------------------------------------------------
__global__ void __launch_bounds__(512) cvtw_k(const float* __restrict__ w) {
    const int j    = blockIdx.x * 512 + threadIdx.x;    // over g_wtp linear
    const int oct  = j >> 11;           // / (256*8)
    const int rem  = j & 2047;
    const int o    = rem >> 3;
    const int slot = rem & 7;
    const int r7   = (slot >> 1) + ((slot & 1) << 2);
    const int r    = oct * 8 + r7;
    const int k2   = r >> 8;
    const int c    = r & 255;
    g_wtp[j] = __uint_as_float(f2tf(w[o * R + c * 9 + k2]));
}

// ---------------------------------------------------------------------------
// Kernel 1: transpose x[b][c][s] -> g_xt[b][s][c]
// ---------------------------------------------------------------------------
__global__ void __launch_bounds__(256) trans_k(const float* __restrict__ x) {
    __shared__ float t[32][33];
    const int b  = blockIdx.z;
    const int s0 = blockIdx.x * 32;
    const int c0 = blockIdx.y * 32;
    const int tx = threadIdx.x, ty = threadIdx.y;
    const float* xb = x + ((size_t)b << 20);
#pragma unroll
    for (int i = ty; i < 32; i += 8)
        t[i][tx] = xb[(size_t)(c0 + i) * S + s0 + tx];
    __syncthreads();
    float* xtb = g_xt + ((size_t)b << 20);
#pragma unroll
    for (int i = ty; i < 32; i += 8)
        xtb[(size_t)(s0 + i) * CIN + c0 + tx] = t[tx][i];
}

// ---------------------------------------------------------------------------
// Kernel 2: im2colT — coalesced gather; one warp per output position s.
//   g_colT[b][s][k2*256+c] = tf32( bilinear(x, s, k2)[c] )
// ---------------------------------------------------------------------------
__global__ void __launch_bounds__(256) im2colT_k(const float* __restrict__ off) {
    const int warp = threadIdx.x >> 5;
    const int lane = threadIdx.x & 31;
    const int s = blockIdx.x * 8 + warp;
    const int b = blockIdx.y;
    const int ho = s >> 6, wo = s & 63;

    const float* Xb = g_xt + ((size_t)b << 20);
    float* op = g_colT + ((size_t)b * S + s) * R;

#pragma unroll
    for (int k2 = 0; k2 < K2; k2++) {
        const float dy = off[((size_t)b * 18 + 2 * k2)     * S + s];
        const float dx = off[((size_t)b * 18 + 2 * k2 + 1) * S + s];
        const float py = (float)(ho - 1 + k2 / 3) + dy;
        const float px = (float)(wo - 1 + k2 % 3) + dx;
        const float yf = floorf(py), xf = floorf(px);
        const int y0 = (int)yf, x0 = (int)xf;
        const float ly = py - yf, lx = px - xf;
        const float hy = 1.0f - ly, hx = 1.0f - lx;
        const bool vy0 = (y0 >= 0)  && (y0 < H);
        const bool vy1 = (y0 >= -1) && (y0 < H - 1);
        const bool vx0 = (x0 >= 0)  && (x0 < W);
        const bool vx1 = (x0 >= -1) && (x0 < W - 1);
        const float w00 = hy * hx * (float)(vy0 && vx0);
        const float w01 = hy * lx * (float)(vy0 && vx1);
        const float w10 = ly * hx * (float)(vy1 && vx0);
        const float w11 = ly * lx * (float)(vy1 && vx1);
        const int cy0 = min(max(y0, 0), H - 1);
        const int cy1 = min(max(y0 + 1, 0), H - 1);
        const int cx0 = min(max(x0, 0), W - 1);
        const int cx1 = min(max(x0 + 1, 0), W - 1);
        const float* p00 = Xb + (((size_t)(cy0 << 6) + cx0) << 8);
        const float* p01 = Xb + (((size_t)(cy0 << 6) + cx1) << 8);
        const float* p10 = Xb + (((size_t)(cy1 << 6) + cx0) << 8);
        const float* p11 = Xb + (((size_t)(cy1 << 6) + cx1) << 8);
        unsigned* od = (unsigned*)(op + (k2 << 8));

#pragma unroll
        for (int half = 0; half < 2; half++) {
            const int c = half * 128 + lane * 4;
            float4 a  = *(const float4*)(p00 + c);
            float4 bb = *(const float4*)(p01 + c);
            float4 cc = *(const float4*)(p10 + c);
            float4 dd = *(const float4*)(p11 + c);
            uint4 v;
            v.x = f2tf(w00 * a.x + w01 * bb.x + w10 * cc.x + w11 * dd.x);
            v.y = f2tf(w00 * a.y + w01 * bb.y + w10 * cc.y + w11 * dd.y);
            v.z = f2tf(w00 * a.z + w01 * bb.z + w10 * cc.z + w11 * dd.z);
            v.w = f2tf(w00 * a.w + w01 * bb.w + w10 * cc.w + w11 * dd.w);
            *(uint4*)(od + c) = v;
        }
    }
}

// ---------------------------------------------------------------------------
// Kernel 3: GEMM  C[b][s][o] = sum_r colT[b][s][r] * W[o][r]   (tf32 mma.sync)
//   CTA tile: 128 s x 128 o, 4 warps, warp tile 64x64, kTile 32, 3-stage cp.async.
//   Epilogue transposes C tile through smem -> out[b][o][s] coalesced.
// ---------------------------------------------------------------------------
#define KTILE 32
#define NKT   72
#define A_LD  36                       // 32 + 4 pad
#define A_STW (128 * A_LD)             // 4608 words
#define B_STW (4 * 128 * 8)            // 4096 words (4 octets x 128 o x 8)
#define STW   (A_STW + B_STW)          // 8704 words
#define STAGES 3
#define SMEM_BYTES (STAGES * STW * 4)  // 104,448 B  (epilogue stg 67,584 B fits)

#define CP_ASYNC16(dst, src) \
    asm volatile("cp.async.cg.shared.global [%0], [%1], 16;\n" :: "r"(dst), "l"(src))
#define CP_COMMIT() asm volatile("cp.async.commit_group;\n")
#define CP_WAIT2()  asm volatile("cp.async.wait_group 2;\n")

__device__ __forceinline__ void mma8(float* c, const unsigned* a, const unsigned* b) {
    asm volatile(
        "mma.sync.aligned.m16n8k8.row.col.f32.tf32.tf32.f32 "
        "{%0,%1,%2,%3}, {%4,%5,%6,%7}, {%8,%9}, {%0,%1,%2,%3};\n"
        : "+f"(c[0]), "+f"(c[1]), "+f"(c[2]), "+f"(c[3])
        : "r"(a[0]), "r"(a[1]), "r"(a[2]), "r"(a[3]), "r"(b[0]), "r"(b[1]));
}

__global__ void __launch_bounds__(128, 2) gemm_k(float* __restrict__ out) {
    extern __shared__ unsigned sm[];
    const unsigned smem_base = (unsigned)__cvta_generic_to_shared(sm);

    const int b     = blockIdx.z;
    const int mBase = blockIdx.x * 128;     // s
    const int nBase = blockIdx.y * 128;     // o

    const int tid  = threadIdx.x;
    const int warp = tid >> 5;
    const int lane = tid & 31;
    const int wm   = (warp >> 1) * 64;      // warp s offset (0/64)
    const int wn   = (warp & 1) * 64;       // warp o offset (0/64)
    const int g    = lane >> 2;
    const int tig  = lane & 3;

    const float* gA = g_colT + ((size_t)b * S + mBase) * R;

    float acc[4][8][4];
#pragma unroll
    for (int i = 0; i < 4; i++)
#pragma unroll
        for (int j = 0; j < 8; j++)
#pragma unroll
            for (int k = 0; k < 4; k++) acc[i][j][k] = 0.0f;

    // ---- stage fill: A 128s x 32k (padded), B 4oct x 128o x 8 (permuted) ----
    auto fill = [&](int st, int kt) {
        const int kb = kt * KTILE;
        const unsigned sa = smem_base + st * (STW * 4);
        const unsigned sb = sa + A_STW * 4;
#pragma unroll
        for (int i = 0; i < 8; i++) {        // A: 1024 x 16B granules
            const int gdx = i * 128 + tid;
            const int r = gdx >> 3, c4 = gdx & 7;
            CP_ASYNC16(sa + ((r * A_LD + c4 * 4) << 2),
                       gA + (size_t)r * R + kb + c4 * 4);
        }
        const float* gBk = g_wtp + ((size_t)(kb >> 3) * COUT + nBase) * 8;
#pragma unroll
        for (int i = 0; i < 8; i++) {        // B: 1024 x 16B granules
            const int gdx = i * 128 + tid;
            const int oct = gdx >> 8;
            const int rem = gdx & 255;
            const int ol  = rem >> 1;
            const int hf  = rem & 1;
            CP_ASYNC16(sb + (((oct * 128 + ol) * 8 + hf * 4) << 2),
                       gBk + ((size_t)oct * COUT + ol) * 8 + hf * 4);
        }
    };

    fill(0, 0); CP_COMMIT();
    fill(1, 1); CP_COMMIT();

    for (int kt = 0; kt < NKT; kt++) {
        __syncthreads();                      // stage (kt+2)%3 free (compute kt-1 done)
        const int pf = kt + 2;
        if (pf < NKT) {
            int pst = kt + 2; pst -= (pst / STAGES) * STAGES;
            fill(pst, pf);
        }
        CP_COMMIT();
        CP_WAIT2();                           // group kt complete
        __syncthreads();

        int cs = kt - (kt / STAGES) * STAGES;
        const unsigned* A  = sm + cs * STW;
        const unsigned* Bm = A + A_STW;

#pragma unroll
        for (int ks = 0; ks < 4; ks++) {
            const int kk = ks * 8 + tig;
            unsigned af[4][4], bf[8][2];
#pragma unroll
            for (int mt = 0; mt < 4; mt++) {
                const int base = (wm + mt * 16 + g) * A_LD + kk;
                af[mt][0] = A[base];
                af[mt][1] = A[base + 8 * A_LD];
                af[mt][2] = A[base + 4];
                af[mt][3] = A[base + 8 * A_LD + 4];
            }
#pragma unroll
            for (int nt = 0; nt < 8; nt++) {
                const int nc = wn + nt * 8 + g;
                uint2 t = *(const uint2*)(Bm + ((ks * 128 + nc) << 3) + (tig << 1));
                bf[nt][0] = t.x;
                bf[nt][1] = t.y;
            }
#pragma unroll
            for (int mt = 0; mt < 4; mt++)
#pragma unroll
                for (int nt = 0; nt < 8; nt++)
                    mma8(acc[mt][nt], af[mt], bf[nt]);
        }
    }

    // ---- epilogue: transpose C[s][o] tile -> out[b][o][s] via smem ----
    __syncthreads();
    float* stg = (float*)sm;                  // [128 o][132]
#pragma unroll
    for (int mt = 0; mt < 4; mt++) {
#pragma unroll
        for (int nt = 0; nt < 8; nt++) {
            const int ol = wn + nt * 8 + 2 * tig;
            const int sl = wm + mt * 16 + g;
            stg[ol * 132 + sl]             = acc[mt][nt][0];
            stg[(ol + 1) * 132 + sl]       = acc[mt][nt][1];
            stg[ol * 132 + sl + 8]         = acc[mt][nt][2];
            stg[(ol + 1) * 132 + sl + 8]   = acc[mt][nt][3];
        }
    }
    __syncthreads();

    float* ob = out + ((size_t)b * COUT + nBase) * S + mBase;
#pragma unroll
    for (int i = 0; i < 32; i++) {
        const int e  = i * 128 + tid;
        const int o  = e >> 5;
        const int l4 = e & 31;
        *(float4*)(ob + (size_t)o * S + 4 * l4) = *(float4*)&stg[o * 132 + 4 * l4];
    }
}

// ---------------------------------------------------------------------------
extern "C" void kernel_launch(void* const* d_in, const int* in_sizes, int n_in,
                              void* d_out, int out_size) {
    const float* x   = (const float*)d_in[0];
    const float* off = (const float*)d_in[1];
    const float* wt  = (const float*)d_in[2];
    float* out       = (float*)d_out;

    cvtw_k<<<(COUT * R) / 512, 512>>>(wt);
    trans_k<<<dim3(S / 32, CIN / 32, BATCH), dim3(32, 8)>>>(x);
    im2colT_k<<<dim3(S / 8, BATCH), 256>>>(off);

    cudaFuncSetAttribute(gemm_k, cudaFuncAttributeMaxDynamicSharedMemorySize,
                         SMEM_BYTES);
    gemm_k<<<dim3(S / 128, COUT / 128, BATCH), 128, SMEM_BYTES>>>(out);
}